// round 3
// baseline (speedup 1.0000x reference)
#include <cuda_runtime.h>
#include <cuda_fp16.h>
#include <cstdint>
#include <cstddef>

// ============================================================================
// AttentionNetwork: P=4096 paths, LMAX=64, D=512, H=512
// tcgen05 is PTX-gated off (compute_103 target) -> mma.sync m16n8k16 fp16
// (10-bit mantissa: precision of tf32 at 2 B/elem; bf16 failed at 1.57e-3).
// Stage 1: per-2-path CTA: X[128,512]->fp16 SMEM, GEMM vs W1^T (chunked,
//          cp.async double buffer), fold relu(.)+b1 dot w2 into 128 scores,
//          masked softmax per path, weighted sum of X -> paths_fea.
// Stage 2: same GEMM on paths_fea -> logits -> softmax over P -> weighted sum.
// ============================================================================

#define NPATHS 4096

// ---------------- device scratch --------------------------------------------
__device__ __half g_W1T[512 * 512];   // pW1^T  [n][k]
__device__ __half g_aW1T[512 * 512];  // aW1^T  [n][k]
__device__ float g_pf[NPATHS * 512];  // paths_fea
__device__ float g_a[NPATHS];         // path logits
__device__ float g_aw[NPATHS];        // path softmax weights
__device__ float g_part[64 * 512];    // reduction partials

// ---------------- SMEM layout (bytes) ----------------------------------------
#define OFF_SC   0            // 128 floats
#define OFF_WTS  512          // 128 floats
#define OFF_B1   1024         // 512 floats
#define OFF_W2   3072         // 512 floats
#define OFF_XS   5120         // 128 rows x 520 fp16 (1040 B stride) = 133120
#define OFF_WS   138240       // 2 bufs x 32 rows x 1040 B = 66560
#define WS_BUF   33280
#define XSTRIDE  1040
#define SMEM_BYTES 204800

// ---------------- PTX helpers ------------------------------------------------
__device__ __forceinline__ uint32_t smem_u32(const void* p) {
    uint32_t a;
    asm("{ .reg .u64 t; cvta.to.shared.u64 t, %1; cvt.u32.u64 %0, t; }"
        : "=r"(a) : "l"(p));
    return a;
}

__device__ __forceinline__ void ldsm4(uint32_t* r, uint32_t addr) {
    asm volatile("ldmatrix.sync.aligned.m8n8.x4.shared.b16 {%0,%1,%2,%3}, [%4];"
                 : "=r"(r[0]), "=r"(r[1]), "=r"(r[2]), "=r"(r[3]) : "r"(addr));
}

__device__ __forceinline__ void mma_f16(float* c, const uint32_t* a,
                                        uint32_t b0, uint32_t b1) {
    asm volatile(
        "mma.sync.aligned.m16n8k16.row.col.f32.f16.f16.f32 "
        "{%0,%1,%2,%3}, {%4,%5,%6,%7}, {%8,%9}, {%0,%1,%2,%3};"
        : "+f"(c[0]), "+f"(c[1]), "+f"(c[2]), "+f"(c[3])
        : "r"(a[0]), "r"(a[1]), "r"(a[2]), "r"(a[3]), "r"(b0), "r"(b1));
}

#define CP_ASYNC16(dst, src) \
    asm volatile("cp.async.cg.shared.global [%0], [%1], 16;" \
                 :: "r"(dst), "l"(src) : "memory")
#define CP_COMMIT() asm volatile("cp.async.commit_group;" ::: "memory")
#define CP_WAIT(n)  asm volatile("cp.async.wait_group %0;" :: "n"(n) : "memory")

// ---------------- shared device pieces ---------------------------------------

// 128 rows x 512 fp32 -> fp16 into Xs [row][520]
__device__ __forceinline__ void load_X_f16(const float* __restrict__ src,
                                           char* smem) {
    int tid = threadIdx.x;
#pragma unroll 4
    for (int i = 0; i < 64; i++) {
        int idx = tid + i * 256;          // 0..16383 float4 slots
        int m = idx >> 7;                 // 128 float4 per row
        int q = idx & 127;
        float4 v = *(const float4*)(src + (size_t)m * 512 + q * 4);
        __half2 p0, p1;
        p0.x = __float2half_rn(v.x); p0.y = __float2half_rn(v.y);
        p1.x = __float2half_rn(v.z); p1.y = __float2half_rn(v.w);
        uint2 st;
        st.x = *(uint32_t*)&p0;
        st.y = *(uint32_t*)&p1;
        *(uint2*)(smem + OFF_XS + m * XSTRIDE + q * 8) = st;
    }
}

// prefetch one W chunk: 32 n-rows x 512 fp16 -> Ws[buf]
__device__ __forceinline__ void prefetch_W(const __half* __restrict__ Wt,
                                           int chunk, int buf, uint32_t sb) {
    int tid = threadIdx.x;
    const __half* src = Wt + (size_t)chunk * 32 * 512;
#pragma unroll
    for (int i = 0; i < 8; i++) {
        int idx = tid + i * 256;          // 0..2047 16B slots
        int nl = idx >> 6;                // 64 x 16B per row
        int q  = idx & 63;
        uint32_t dst = sb + OFF_WS + buf * WS_BUF + nl * XSTRIDE + q * 16;
        CP_ASYNC16(dst, src + (size_t)nl * 512 + q * 8);
    }
    CP_COMMIT();
}

// GEMM [128x512] @ W^T[512x512] folded to scores. Xs must be loaded, b1s/w2s
// in SMEM, sc[] zeroed, all synced. On exit (after final __syncthreads)
// sc[m] = sum_n relu(h[m][n]+b1[n])*w2[n].
__device__ __forceinline__ void gemm_scores(char* smem, uint32_t sb,
                                            const __half* __restrict__ Wt) {
    int tid = threadIdx.x;
    int lane = tid & 31, wid = tid >> 5;
    int warp_m = wid & 3;                 // 32-row M slice
    int warp_n = wid >> 2;                // 16-col N half of 32-chunk
    const float* b1s = (const float*)(smem + OFF_B1);
    const float* w2s = (const float*)(smem + OFF_W2);
    float* sc = (float*)(smem + OFF_SC);

    // per-lane ldmatrix base addresses
    int lr = lane & 7;
    // A: tiles (rows0-7,k0)(rows8-15,k0)(rows0-7,k8)(rows8-15,k8)
    uint32_t a_row = warp_m * 32 + ((lane >> 3) & 1) * 8 + lr;
    uint32_t a_kb  = (lane >> 4) * 16;
    uint32_t aAddr0 = sb + OFF_XS + a_row * XSTRIDE + a_kb;
    uint32_t aAddr1 = aAddr0 + 16 * XSTRIDE;
    // B: tiles (n0-7,k0)(n0-7,k8)(n8-15,k0)(n8-15,k8)
    uint32_t b_row = warp_n * 16 + (lane >> 4) * 8 + lr;
    uint32_t b_kb  = ((lane >> 3) & 1) * 16;
    uint32_t bAddrBase = sb + OFF_WS + b_row * XSTRIDE + b_kb;

    float acc[2][2][4];
#pragma unroll
    for (int i = 0; i < 2; i++)
#pragma unroll
        for (int j = 0; j < 2; j++)
#pragma unroll
            for (int q = 0; q < 4; q++) acc[i][j][q] = 0.f;
    float rs[4] = {0.f, 0.f, 0.f, 0.f};

    prefetch_W(Wt, 0, 0, sb);

    for (int c = 0; c < 16; c++) {
        if (c + 1 < 16) prefetch_W(Wt, c + 1, (c + 1) & 1, sb);
        if (c + 1 < 16) { CP_WAIT(1); } else { CP_WAIT(0); }
        __syncthreads();

        uint32_t bAddr = bAddrBase + (c & 1) * WS_BUF;
#pragma unroll
        for (int k = 0; k < 32; k++) {
            uint32_t a0[4], a1[4], b[4];
            ldsm4(a0, aAddr0 + k * 32);
            ldsm4(a1, aAddr1 + k * 32);
            ldsm4(b,  bAddr  + k * 32);
            mma_f16(acc[0][0], a0, b[0], b[1]);
            mma_f16(acc[0][1], a0, b[2], b[3]);
            mma_f16(acc[1][0], a1, b[0], b[1]);
            mma_f16(acc[1][1], a1, b[2], b[3]);
        }

        // fold this 32-wide N chunk into per-row score partials
        int t2 = (lane & 3) * 2;
#pragma unroll
        for (int nf = 0; nf < 2; nf++) {
            int n0 = c * 32 + warp_n * 16 + nf * 8 + t2;
            float bb0 = b1s[n0], bb1 = b1s[n0 + 1];
            float ww0 = w2s[n0], ww1 = w2s[n0 + 1];
#pragma unroll
            for (int mf = 0; mf < 2; mf++) {
                float* cc = acc[mf][nf];
                rs[mf * 2 + 0] += fmaxf(cc[0] + bb0, 0.f) * ww0 +
                                  fmaxf(cc[1] + bb1, 0.f) * ww1;
                rs[mf * 2 + 1] += fmaxf(cc[2] + bb0, 0.f) * ww0 +
                                  fmaxf(cc[3] + bb1, 0.f) * ww1;
                cc[0] = cc[1] = cc[2] = cc[3] = 0.f;
            }
        }
        __syncthreads();   // chunk buffer free for reuse
    }

    // reduce over the 4 lanes sharing a row group, then combine N-halves
#pragma unroll
    for (int i = 0; i < 4; i++) {
        rs[i] += __shfl_xor_sync(0xffffffffu, rs[i], 1);
        rs[i] += __shfl_xor_sync(0xffffffffu, rs[i], 2);
    }
    if ((lane & 3) == 0) {
        int g = lane >> 2;
        atomicAdd(&sc[warp_m * 32 + g],      rs[0]);
        atomicAdd(&sc[warp_m * 32 + g + 8],  rs[1]);
        atomicAdd(&sc[warp_m * 32 + g + 16], rs[2]);
        atomicAdd(&sc[warp_m * 32 + g + 24], rs[3]);
    }
    __syncthreads();
}

// ---------------- kernel 0: transpose + convert weights ----------------------
__global__ void k_conv(const float* __restrict__ pW1,
                       const float* __restrict__ aW1) {
    __shared__ float tile[64][65];
    const float* src = blockIdx.z ? aW1 : pW1;
    __half* dst = blockIdx.z ? g_aW1T : g_W1T;
    int k0 = blockIdx.y * 64, n0 = blockIdx.x * 64;
    for (int i = threadIdx.x; i < 4096; i += 256) {
        int r = i >> 6, cth = i & 63;
        tile[r][cth] = src[(size_t)(k0 + r) * 512 + n0 + cth];
    }
    __syncthreads();
    for (int i = threadIdx.x; i < 4096; i += 256) {
        int r = i >> 6, cth = i & 63;
        dst[(size_t)(n0 + r) * 512 + k0 + cth] = __float2half_rn(tile[cth][r]);
    }
}

// ---------------- kernel 1: fused per-2-path stage ----------------------------
__global__ void __launch_bounds__(256, 1)
k_path(const float* __restrict__ nodes, const int* __restrict__ lengths,
       const float* __restrict__ pb1, const float* __restrict__ pw2,
       const float* __restrict__ pb2) {
    extern __shared__ char smem[];
    uint32_t sb = smem_u32(smem);
    int tid = threadIdx.x;

    float* b1s = (float*)(smem + OFF_B1);
    float* w2s = (float*)(smem + OFF_W2);
    float* sc  = (float*)(smem + OFF_SC);
    for (int i = tid; i < 512; i += 256) { b1s[i] = pb1[i]; w2s[i] = pw2[i]; }
    if (tid < 128) sc[tid] = 0.f;

    const float* X = nodes + (size_t)blockIdx.x * 128 * 512;
    load_X_f16(X, smem);
    __syncthreads();

    gemm_scores(smem, sb, g_W1T);

    // per-path masked softmax over 64 positions
    if (tid < 128) {
        int pl = tid >> 6, l = tid & 63;
        int len = lengths[blockIdx.x * 2 + pl];
        const float* ss = sc + pl * 64;
        float mx = -1e30f;
        for (int j = 0; j < 64; j++) if (j < len) mx = fmaxf(mx, ss[j]);
        float sum = 0.f;
        for (int j = 0; j < 64; j++) if (j < len) sum += expf(ss[j] - mx);
        float w = (l < len) ? expf(ss[l] - mx) / sum : 0.f;
        ((float*)(smem + OFF_WTS))[tid] = w;
    }
    __syncthreads();

    // weighted sum of X rows (fp16 in SMEM) -> paths_fea
    const float* wts = (const float*)(smem + OFF_WTS);
#pragma unroll
    for (int it = 0; it < 2; it++) {
        int pl = tid >> 7;
        int dp = (tid & 127) + it * 128;       // fp16x2 column (0..255)
        float a0 = 0.f, a1 = 0.f;
        const char* base = smem + OFF_XS + dp * 4;
        for (int l = 0; l < 64; l++) {
            int m = pl * 64 + l;
            uint32_t v = *(const uint32_t*)(base + m * XSTRIDE);
            __half2 hv = *(__half2*)&v;
            float wl = wts[m];
            a0 = fmaf(wl, __half2float(hv.x), a0);
            a1 = fmaf(wl, __half2float(hv.y), a1);
        }
        float* dst = g_pf + ((size_t)blockIdx.x * 2 + pl) * 512 + dp * 2;
        dst[0] = a0;
        dst[1] = a1;
    }
}

// ---------------- kernel 2: path-level MLP logits -----------------------------
__global__ void __launch_bounds__(256, 1)
k_agg(const float* __restrict__ ab1, const float* __restrict__ aw2,
      const float* __restrict__ ab2) {
    extern __shared__ char smem[];
    uint32_t sb = smem_u32(smem);
    int tid = threadIdx.x;

    float* b1s = (float*)(smem + OFF_B1);
    float* w2s = (float*)(smem + OFF_W2);
    float* sc  = (float*)(smem + OFF_SC);
    for (int i = tid; i < 512; i += 256) { b1s[i] = ab1[i]; w2s[i] = aw2[i]; }
    if (tid < 128) sc[tid] = 0.f;

    const float* X = g_pf + (size_t)blockIdx.x * 128 * 512;
    load_X_f16(X, smem);
    __syncthreads();

    gemm_scores(smem, sb, g_aW1T);

    if (tid < 128) g_a[blockIdx.x * 128 + tid] = sc[tid] + ab2[0];
}

// ---------------- kernel 3: softmax over 4096 paths ---------------------------
__global__ void k_soft() {
    __shared__ float red[1024];
    int t = threadIdx.x;
    float m = -1e30f;
    for (int i = t; i < NPATHS; i += 1024) m = fmaxf(m, g_a[i]);
    red[t] = m;
    __syncthreads();
    for (int s = 512; s > 0; s >>= 1) {
        if (t < s) red[t] = fmaxf(red[t], red[t + s]);
        __syncthreads();
    }
    float M = red[0];
    __syncthreads();
    float sum = 0.f;
    for (int i = t; i < NPATHS; i += 1024) sum += expf(g_a[i] - M);
    red[t] = sum;
    __syncthreads();
    for (int s = 512; s > 0; s >>= 1) {
        if (t < s) red[t] += red[t + s];
        __syncthreads();
    }
    float S = red[0];
    for (int i = t; i < NPATHS; i += 1024) g_aw[i] = expf(g_a[i] - M) / S;
}

// ---------------- kernel 4: partial weighted sums -----------------------------
__global__ void k_red() {
    int b = blockIdx.x, t = threadIdx.x;
    float a0 = 0.f, a1 = 0.f;
    for (int p = 0; p < 64; p++) {
        int pg = b * 64 + p;
        float w = g_aw[pg];
        const float* row = g_pf + (size_t)pg * 512;
        a0 = fmaf(w, row[t], a0);
        a1 = fmaf(w, row[t + 256], a1);
    }
    g_part[(size_t)b * 512 + t] = a0;
    g_part[(size_t)b * 512 + t + 256] = a1;
}

// ---------------- kernel 5: final reduction -----------------------------------
__global__ void k_fin(float* __restrict__ out) {
    int t = threadIdx.x;
    float s = 0.f;
    for (int b = 0; b < 64; b++) s += g_part[(size_t)b * 512 + t];
    out[t] = s;
}

// ---------------- entry -------------------------------------------------------
extern "C" void kernel_launch(void* const* d_in, const int* in_sizes, int n_in,
                              void* d_out, int out_size) {
    const float* nodes   = (const float*)d_in[0];
    const int*   lengths = (const int*)  d_in[1];
    const float* pW1     = (const float*)d_in[2];
    const float* pb1     = (const float*)d_in[3];
    const float* pw2     = (const float*)d_in[4];
    const float* pb2     = (const float*)d_in[5];
    const float* aW1     = (const float*)d_in[6];
    const float* ab1     = (const float*)d_in[7];
    const float* aw2     = (const float*)d_in[8];
    const float* ab2     = (const float*)d_in[9];
    float* out = (float*)d_out;

    cudaFuncSetAttribute(k_path, cudaFuncAttributeMaxDynamicSharedMemorySize, SMEM_BYTES);
    cudaFuncSetAttribute(k_agg,  cudaFuncAttributeMaxDynamicSharedMemorySize, SMEM_BYTES);

    k_conv<<<dim3(8, 8, 2), 256>>>(pW1, aW1);
    k_path<<<NPATHS / 2, 256, SMEM_BYTES>>>(nodes, lengths, pb1, pw2, pb2);
    k_agg<<<NPATHS / 128, 256, SMEM_BYTES>>>(ab1, aw2, ab2);
    k_soft<<<1, 1024>>>();
    k_red<<<64, 256>>>();
    k_fin<<<1, 512>>>(out);
}